// round 2
// baseline (speedup 1.0000x reference)
#include <cuda_runtime.h>
#include <cuda_bf16.h>
#include <stdint.h>

// Problem constants
#define NB      32
#define NN      64
#define MV      2080          // NN*(NN+1)/2
#define MSORT   4096          // padded power of two
#define TOPK    5
#define NEIGHBOR 16
#define NEGATIVE 16
#define TOTAL   85            // TOPK*(NEIGHBOR+1)
#define KOUT    101           // NEGATIVE + TOTAL
#define DFEAT   512

// dynamic smem layout (byte offsets)
#define OFF_KEY     0                       // u64  [4096]   32768
#define OFF_SS      32768                   // u16  [2080]    4160
#define OFF_EE      36928                   // u16  [2080]    4160
#define OFF_RR      41088                   // u8   [2080]    2080
#define OFF_CC      43168                   // u8   [2080]    2080
#define OFF_SUP     45248                   // u8   [2080]    2080
#define OFF_SEL     47328                   // u8   [2080]    2080
#define OFF_UNSUP   49408                   // u16  [2080]    4160
#define OFF_SELIDX  53568                   // u16  [96]       192
#define OFF_WSUM    53760                   // int  [33]       132 (pad 136)
#define OFF_FR      53896                   // int  [101]      404
#define OFF_FC      54300                   // int  [101]      404
#define SMEM_BYTES  55296

template<bool WANT_TRUE>
__device__ __forceinline__ int compact2080(const unsigned char* flags,
                                           unsigned short* out, int* wsum) {
    int tid = threadIdx.x, lane = tid & 31, wid = tid >> 5;
    bool pr[3]; int local = 0;
#pragma unroll
    for (int u = 0; u < 3; u++) {
        int j = 3 * tid + u;
        bool f = (j < MV) && ((flags[j] != 0) == WANT_TRUE);
        pr[u] = f; local += (int)f;
    }
    int x = local;
#pragma unroll
    for (int d = 1; d < 32; d <<= 1) {
        int y = __shfl_up_sync(0xffffffffu, x, d);
        if (lane >= d) x += y;
    }
    if (lane == 31) wsum[wid] = x;   // inclusive warp totals
    __syncthreads();
    if (wid == 0) {
        int v = wsum[lane];
        int xx = v;
#pragma unroll
        for (int d = 1; d < 32; d <<= 1) {
            int y = __shfl_up_sync(0xffffffffu, xx, d);
            if (lane >= d) xx += y;
        }
        wsum[lane] = xx - v;          // exclusive
        if (lane == 31) wsum[32] = xx; // grand total
    }
    __syncthreads();
    int base = wsum[wid] + x - local;
#pragma unroll
    for (int u = 0; u < 3; u++) {
        if (pr[u]) out[base++] = (unsigned short)(3 * tid + u);
    }
    int total = wsum[32];
    __syncthreads();   // protect wsum for reuse
    return total;
}

__global__ __launch_bounds__(1024, 1)
void aps_kernel(const float* __restrict__ score_pred,
                const float* __restrict__ map2d,
                const float* __restrict__ offset_gt,
                const float* __restrict__ tmap,
                float* __restrict__ out) {
    extern __shared__ char smem[];
    unsigned long long* key = (unsigned long long*)(smem + OFF_KEY);
    unsigned short* ss   = (unsigned short*)(smem + OFF_SS);
    unsigned short* ee   = (unsigned short*)(smem + OFF_EE);
    unsigned char*  rr   = (unsigned char*) (smem + OFF_RR);
    unsigned char*  cc   = (unsigned char*) (smem + OFF_CC);
    unsigned char*  sup  = (unsigned char*) (smem + OFF_SUP);
    unsigned char*  sel  = (unsigned char*) (smem + OFF_SEL);
    unsigned short* unsupIdx = (unsigned short*)(smem + OFF_UNSUP);
    unsigned short* selIdx   = (unsigned short*)(smem + OFF_SELIDX);
    int* wsum = (int*)(smem + OFF_WSUM);
    int* fr   = (int*)(smem + OFF_FR);
    int* fc   = (int*)(smem + OFF_FC);

    const int b   = blockIdx.x;
    const int tid = threadIdx.x;
    const int lane = tid & 31, wid = tid >> 5;

    // --- 1. (r,c) tables for triu mask in row-major nonzero order ---
    if (tid < NN) {
        int r = tid;
        int base = r * NN - (r * (r - 1)) / 2;
        for (int c = r; c < NN; c++) {
            int p = base + (c - r);
            rr[p] = (unsigned char)r;
            cc[p] = (unsigned char)c;
        }
    }
    __syncthreads();

    // --- 2. build sort keys: (orderable_float << 32) | original_index ---
    for (int p = tid; p < MSORT; p += 1024) {
        unsigned long long kv = 0ull;
        if (p < MV) {
            int r = rr[p], c = cc[p];
            float s = score_pred[((size_t)b * NN + r) * NN + c];
            unsigned ub = __float_as_uint(s);
            ub = (ub & 0x80000000u) ? ~ub : (ub | 0x80000000u);
            kv = ((unsigned long long)ub << 32) | (unsigned)p;
        }
        key[p] = kv;
    }

    // --- 3. bitonic sort DESCENDING on u64 keys ---
    for (int k = 2; k <= MSORT; k <<= 1) {
        for (int j = k >> 1; j > 0; j >>= 1) {
            __syncthreads();
            for (int i = tid; i < MSORT; i += 1024) {
                int ixj = i ^ j;
                if (ixj > i) {
                    unsigned long long a = key[i], bb = key[ixj];
                    bool upseg = ((i & k) == 0);
                    bool doswap = upseg ? (a < bb) : (a > bb);
                    if (doswap) { key[i] = bb; key[ixj] = a; }
                }
            }
        }
    }
    __syncthreads();

    // --- 4. sorted moment arrays + clear bitmaps ---
    for (int i = tid; i < MV; i += 1024) {
        int orig = (int)(unsigned)(key[i] & 0xFFFFFFFFull);
        ss[i] = rr[orig];
        ee[i] = (unsigned short)(cc[orig] + 1);
        sup[i] = 0; sel[i] = 0;
    }
    __syncthreads();

    // --- 5. NMS selection loop (warp 0 only) ---
    if (wid == 0) {
        int i = 0, cnt = 0;
        while (cnt < TOPK) {
            // next free pivot in [i, MV-2]
            int piv = -1;
            for (int base = i; base < MV - 1; base += 32) {
                int j = base + lane;
                bool ok = (j < MV - 1) && (sup[j] == 0);
                unsigned bl = __ballot_sync(0xffffffffu, ok);
                if (bl) { piv = base + __ffs(bl) - 1; break; }
            }
            if (piv < 0) break;
            int s_i = ss[piv], e_i = ee[piv];

            // per-lane contiguous chunk of 65 sorted positions
            int localCount = 0;
#pragma unroll 1
            for (int u = 0; u < 65; u++) {
                int j = lane * 65 + u;
                if (j < MV && j > piv) {
                    int inter = min((int)ee[j], e_i) - max((int)ss[j], s_i);
                    int uni   = max((int)ee[j], e_i) - min((int)ss[j], s_i);
                    if (2 * inter > uni) localCount++;
                }
            }
            int x = localCount;
#pragma unroll
            for (int d = 1; d < 32; d <<= 1) {
                int y = __shfl_up_sync(0xffffffffu, x, d);
                if (lane >= d) x += y;
            }
            int run = x - localCount;   // exclusive prefix of masked count
#pragma unroll 1
            for (int u = 0; u < 65; u++) {
                int j = lane * 65 + u;
                if (j < MV && j > piv) {
                    int inter = min((int)ee[j], e_i) - max((int)ss[j], s_i);
                    int uni   = max((int)ee[j], e_i) - min((int)ss[j], s_i);
                    if (2 * inter > uni) {
                        sup[j] = 1;
                        run++;
                        if (run <= NEIGHBOR) sel[j] = 1;
                    }
                }
            }
            if (lane == 0) { sup[piv] = 1; sel[piv] = 1; }
            __syncwarp();
            cnt++;
            i = piv + 1;
        }
    }
    __syncthreads();

    // --- 6. stable compactions ---
    int nUnsup = compact2080<false>(sup, unsupIdx, wsum);   // indices with !sup
    int nSel   = compact2080<true >(sel, selIdx,   wsum);   // indices with sel

    // --- 7. final index assembly + small outputs ---
    float* feat = out;
    float* se   = out + (size_t)NB * KOUT * DFEAT;
    float* off  = se  + (size_t)NB * KOUT * 2;
    float* sc   = off + (size_t)NB * KOUT * 2;

    if (tid < KOUT) {
        int k = tid;
        int val;
        if (k < NEGATIVE) {
            int pos = nUnsup - 1 - k;
            if (pos < 0) pos = 0;
            val = (pos < nUnsup) ? (int)unsupIdx[pos] : (MV - 1);
        } else {
            int p = k - NEGATIVE;
            int pad = TOTAL - nSel;
            if (p < pad) {
                val = (p < nUnsup) ? (int)unsupIdx[p] : (MV - 1);
            } else {
                val = (int)selIdx[p - pad];
            }
        }
        int orig = (int)(unsigned)(key[val] & 0xFFFFFFFFull);
        int r = rr[orig], c = cc[orig];
        fr[k] = r; fc[k] = c;

        size_t o = (size_t)b * KOUT + k;
        se[o * 2 + 0] = (float)r;
        se[o * 2 + 1] = (float)(c + 1);
        size_t cell = ((size_t)b * NN + r) * NN + c;
        off[o * 2 + 0] = offset_gt[cell * 2 + 0];
        off[o * 2 + 1] = offset_gt[cell * 2 + 1];
        sc[o] = tmap[cell];
    }
    __syncthreads();

    // --- 8. feature gather (float4, coalesced 2KB rows) ---
    const float4* src = (const float4*)map2d;
    float4* dst = (float4*)feat;
    const int VEC = DFEAT / 4;   // 128
    for (int t = tid; t < KOUT * VEC; t += 1024) {
        int k = t >> 7;
        int d = t & (VEC - 1);
        int r = fr[k], c = fc[k];
        dst[((size_t)b * KOUT + k) * VEC + d] =
            src[(((size_t)b * NN + r) * NN + c) * VEC + d];
    }
}

extern "C" void kernel_launch(void* const* d_in, const int* in_sizes, int n_in,
                              void* d_out, int out_size) {
    const float* score_pred = (const float*)d_in[0];
    // d_in[1] = map2d_mask (deterministic triu(ones)) — computed analytically
    const float* map2d      = (const float*)d_in[2];
    const float* offset_gt  = (const float*)d_in[3];
    const float* tmap       = (const float*)d_in[4];
    float* out = (float*)d_out;

    cudaFuncSetAttribute(aps_kernel, cudaFuncAttributeMaxDynamicSharedMemorySize,
                         SMEM_BYTES);
    aps_kernel<<<NB, 1024, SMEM_BYTES>>>(score_pred, map2d, offset_gt, tmap, out);
}

// round 4
// speedup vs baseline: 1.5374x; 1.5374x over previous
#include <cuda_runtime.h>
#include <cuda_bf16.h>
#include <stdint.h>

// Problem constants
#define NB      32
#define NN      64
#define MV      2080          // NN*(NN+1)/2
#define MSORT   4096          // padded power of two
#define TOPK    5
#define NEIGHBOR 16
#define NEGATIVE 16
#define TOTAL   85            // TOPK*(NEIGHBOR+1)
#define KOUT    101           // NEGATIVE + TOTAL
#define DFEAT   512

// dynamic smem layout (byte offsets)
#define OFF_KEY     0                       // u64  [4096]   32768
#define OFF_MOM     32768                   // u32  [2080]    8320
#define OFF_RR      41088                   // u8   [2080]    2080
#define OFF_CC      43168                   // u8   [2080]    2080
#define OFF_SUP     45248                   // u8   [2080]    2080
#define OFF_SEL     47328                   // u8   [2080]    2080
#define OFF_UNSUP   49408                   // u16  [2080]    4160
#define OFF_SELIDX  53568                   // u16  [96]       192
#define OFF_WSUM    53760                   // int  [34]       136
#define OFF_FR      53896                   // int  [101]      404
#define OFF_FC      54300                   // int  [101]      404
#define SMEM_BYTES  54784

__device__ __forceinline__ void cas64(unsigned long long& a, unsigned long long& b, bool dir) {
    // dir true -> descending (a >= b)
    unsigned long long x = a, y = b;
    bool sw = dir ? (x < y) : (x > y);
    a = sw ? y : x;
    b = sw ? x : y;
}

// Register/shuffle stages for bitonic merge step k, levels j = J0 down to 1.
// Thread t owns elements i = 4t + v (v=0..3); warp holds 128 consecutive elements.
// J0 must be <= 64 (>=128 handled in smem).
template<int J0>
__device__ __forceinline__ void reg_stages(unsigned long long e[4], int tid, int lane, int k) {
    const int base = tid * 4;
    const bool dirU = ((base & k) == 0);
#pragma unroll
    for (int j = J0; j >= 4; j >>= 1) {
        int lm = j >> 2;
        bool lower = ((lane & lm) == 0);
        bool keepMax = (lower == dirU);
#pragma unroll
        for (int v = 0; v < 4; v++) {
            unsigned long long p = __shfl_xor_sync(0xffffffffu, e[v], lm);
            unsigned long long mx = e[v] > p ? e[v] : p;
            unsigned long long mn = e[v] > p ? p : e[v];
            e[v] = keepMax ? mx : mn;
        }
    }
    if (J0 >= 2) {  // j = 2 : pairs (0,2),(1,3); k >= 4 here so dir uniform
        cas64(e[0], e[2], dirU);
        cas64(e[1], e[3], dirU);
    }
    // j = 1 : pairs (0,1),(2,3)
    if (k == 2) {
        cas64(e[0], e[1], true);    // i&2 == 0
        cas64(e[2], e[3], false);   // i&2 == 2
    } else {
        cas64(e[0], e[1], dirU);
        cas64(e[2], e[3], dirU);
    }
}

__device__ __forceinline__ void smem_pass(unsigned long long* key, int k, int j, int tid) {
    for (int i = tid; i < MSORT; i += 1024) {
        int ixj = i ^ j;
        if (ixj > i) {
            unsigned long long a = key[i], bb = key[ixj];
            bool upseg = ((i & k) == 0);
            bool doswap = upseg ? (a < bb) : (a > bb);
            if (doswap) { key[i] = bb; key[ixj] = a; }
        }
    }
}

template<bool WANT_TRUE>
__device__ __forceinline__ int compact2080(const unsigned char* flags,
                                           unsigned short* out, int* wsum) {
    int tid = threadIdx.x, lane = tid & 31, wid = tid >> 5;
    bool pr[3]; int local = 0;
#pragma unroll
    for (int u = 0; u < 3; u++) {
        int j = 3 * tid + u;
        bool f = (j < MV) && ((flags[j] != 0) == WANT_TRUE);
        pr[u] = f; local += (int)f;
    }
    int x = local;
#pragma unroll
    for (int d = 1; d < 32; d <<= 1) {
        int y = __shfl_up_sync(0xffffffffu, x, d);
        if (lane >= d) x += y;
    }
    if (lane == 31) wsum[wid] = x;   // inclusive warp totals
    __syncthreads();
    if (wid == 0) {
        int v = wsum[lane];
        int xx = v;
#pragma unroll
        for (int d = 1; d < 32; d <<= 1) {
            int y = __shfl_up_sync(0xffffffffu, xx, d);
            if (lane >= d) xx += y;
        }
        wsum[lane] = xx - v;           // exclusive
        if (lane == 31) wsum[32] = xx; // grand total
    }
    __syncthreads();
    int base = wsum[wid] + x - local;
#pragma unroll
    for (int u = 0; u < 3; u++) {
        if (pr[u]) out[base++] = (unsigned short)(3 * tid + u);
    }
    int total = wsum[32];
    __syncthreads();   // protect wsum for reuse
    return total;
}

__global__ __launch_bounds__(1024, 1)
void aps_kernel(const float* __restrict__ score_pred,
                const float* __restrict__ map2d,
                const float* __restrict__ offset_gt,
                const float* __restrict__ tmap,
                float* __restrict__ out) {
    extern __shared__ char smem[];
    unsigned long long* key = (unsigned long long*)(smem + OFF_KEY);
    unsigned*       mom  = (unsigned*)      (smem + OFF_MOM);
    unsigned char*  rr   = (unsigned char*) (smem + OFF_RR);
    unsigned char*  cc   = (unsigned char*) (smem + OFF_CC);
    unsigned char*  sup  = (unsigned char*) (smem + OFF_SUP);
    unsigned char*  sel  = (unsigned char*) (smem + OFF_SEL);
    unsigned short* unsupIdx = (unsigned short*)(smem + OFF_UNSUP);
    unsigned short* selIdx   = (unsigned short*)(smem + OFF_SELIDX);
    int* wsum = (int*)(smem + OFF_WSUM);
    int* fr   = (int*)(smem + OFF_FR);
    int* fc   = (int*)(smem + OFF_FC);

    const int b    = blockIdx.x;
    const int tid  = threadIdx.x;
    const int lane = tid & 31, wid = tid >> 5;

    // --- 1. (r,c) tables for triu mask in row-major nonzero order ---
    if (tid < NN) {
        int r = tid;
        int base = r * NN - (r * (r - 1)) / 2;
        for (int c = r; c < NN; c++) {
            int p = base + (c - r);
            rr[p] = (unsigned char)r;
            cc[p] = (unsigned char)c;
        }
    }
    __syncthreads();

    // --- 2. build sort keys in REGISTERS: (orderable_f32 << 32) | idx ---
    unsigned long long e[4];
#pragma unroll
    for (int v = 0; v < 4; v++) {
        int p = tid * 4 + v;
        unsigned long long kv = 0ull;
        if (p < MV) {
            int r = rr[p], c = cc[p];
            float s = score_pred[((size_t)b * NN + r) * NN + c];
            unsigned ub = __float_as_uint(s);
            ub = (ub & 0x80000000u) ? ~ub : (ub | 0x80000000u);
            kv = ((unsigned long long)ub << 32) | (unsigned)p;
        }
        e[v] = kv;
    }

    // --- 3. bitonic sort DESCENDING, register/shuffle + smem hybrid ---
    reg_stages<1 >(e, tid, lane, 2);
    reg_stages<2 >(e, tid, lane, 4);
    reg_stages<4 >(e, tid, lane, 8);
    reg_stages<8 >(e, tid, lane, 16);
    reg_stages<16>(e, tid, lane, 32);
    reg_stages<32>(e, tid, lane, 64);
    reg_stages<64>(e, tid, lane, 128);

    for (int k = 256; k <= MSORT; k <<= 1) {
        // spill registers to smem
#pragma unroll
        for (int v = 0; v < 4; v++) key[tid * 4 + v] = e[v];
        __syncthreads();
        for (int j = k >> 1; j >= 128; j >>= 1) {
            smem_pass(key, k, j, tid);
            __syncthreads();
        }
        // reload own elements (each location read only by its owner)
#pragma unroll
        for (int v = 0; v < 4; v++) e[v] = key[tid * 4 + v];
        reg_stages<64>(e, tid, lane, k);
    }
    // final publish of sorted keys
#pragma unroll
    for (int v = 0; v < 4; v++) key[tid * 4 + v] = e[v];
    __syncthreads();

    // --- 4. sorted packed moments + clear bitmaps ---
    for (int i = tid; i < MV; i += 1024) {
        int orig = (int)(unsigned)(key[i] & 0xFFFFFFFFull);
        unsigned s = rr[orig];
        unsigned en = (unsigned)cc[orig] + 1u;
        mom[i] = s | (en << 16);
        sup[i] = 0; sel[i] = 0;
    }
    __syncthreads();

    // --- 5. NMS selection loop (warp 0 only) ---
    if (wid == 0) {
        int i = 0, cnt = 0;
        while (cnt < TOPK) {
            // next free pivot in [i, MV-2]
            int piv = -1;
            for (int base = i; base < MV - 1; base += 32) {
                int j = base + lane;
                bool ok = (j < MV - 1) && (sup[j] == 0);
                unsigned bl = __ballot_sync(0xffffffffu, ok);
                if (bl) { piv = base + __ffs(bl) - 1; break; }
            }
            if (piv < 0) break;
            unsigned mp = mom[piv];
            int s_i = (int)(mp & 0xffffu), e_i = (int)(mp >> 16);

            // pass 1: match mask + count (blocked layout: lane owns 65 consecutive)
            unsigned long long mlo = 0ull; unsigned mhi = 0u;
            int localCount = 0;
#pragma unroll 13
            for (int u = 0; u < 65; u++) {
                int j = lane * 65 + u;
                bool match = false;
                if (j < MV && j > piv) {
                    unsigned m = mom[j];
                    int sj = (int)(m & 0xffffu), ej = (int)(m >> 16);
                    int inter = min(ej, e_i) - max(sj, s_i);
                    int uni   = max(ej, e_i) - min(sj, s_i);
                    match = (2 * inter > uni);
                }
                if (match) {
                    localCount++;
                    if (u < 64) mlo |= (1ull << u); else mhi |= 1u;
                }
            }
            int x = localCount;
#pragma unroll
            for (int d = 1; d < 32; d <<= 1) {
                int y = __shfl_up_sync(0xffffffffu, x, d);
                if (lane >= d) x += y;
            }
            int run = x - localCount;   // exclusive prefix of match count
            // pass 2: write flags from cached bits (ALU only + few STS)
#pragma unroll 13
            for (int u = 0; u < 65; u++) {
                bool match = (u < 64) ? (((mlo >> u) & 1ull) != 0ull) : (mhi != 0u);
                if (match) {
                    int j = lane * 65 + u;
                    sup[j] = 1;
                    run++;
                    if (run <= NEIGHBOR) sel[j] = 1;
                }
            }
            if (lane == 0) { sup[piv] = 1; sel[piv] = 1; }
            __syncwarp();
            cnt++;
            i = piv + 1;
        }
    }
    __syncthreads();

    // --- 6. stable compactions ---
    int nUnsup = compact2080<false>(sup, unsupIdx, wsum);   // !sup
    int nSel   = compact2080<true >(sel, selIdx,   wsum);   // sel

    // --- 7. final index assembly + small outputs ---
    float* feat = out;
    float* se   = out + (size_t)NB * KOUT * DFEAT;
    float* off  = se  + (size_t)NB * KOUT * 2;
    float* sc   = off + (size_t)NB * KOUT * 2;

    if (tid < KOUT) {
        int k = tid;
        int val;
        if (k < NEGATIVE) {
            int pos = nUnsup - 1 - k;
            if (pos < 0) pos = 0;
            val = (pos < nUnsup) ? (int)unsupIdx[pos] : (MV - 1);
        } else {
            int p = k - NEGATIVE;
            int pad = TOTAL - nSel;
            if (p < pad) {
                val = (p < nUnsup) ? (int)unsupIdx[p] : (MV - 1);
            } else {
                val = (int)selIdx[p - pad];
            }
        }
        int orig = (int)(unsigned)(key[val] & 0xFFFFFFFFull);
        int r = rr[orig], c = cc[orig];
        fr[k] = r; fc[k] = c;

        size_t o = (size_t)b * KOUT + k;
        se[o * 2 + 0] = (float)r;
        se[o * 2 + 1] = (float)(c + 1);
        size_t cell = ((size_t)b * NN + r) * NN + c;
        off[o * 2 + 0] = offset_gt[cell * 2 + 0];
        off[o * 2 + 1] = offset_gt[cell * 2 + 1];
        sc[o] = tmap[cell];
    }
    __syncthreads();

    // --- 8. feature gather (float4, coalesced 2KB rows) ---
    const float4* src = (const float4*)map2d;
    float4* dst = (float4*)feat;
    const int VEC = DFEAT / 4;   // 128
    for (int t = tid; t < KOUT * VEC; t += 1024) {
        int k = t >> 7;
        int d = t & (VEC - 1);
        int r = fr[k], c = fc[k];
        dst[((size_t)b * KOUT + k) * VEC + d] =
            src[(((size_t)b * NN + r) * NN + c) * VEC + d];
    }
}

extern "C" void kernel_launch(void* const* d_in, const int* in_sizes, int n_in,
                              void* d_out, int out_size) {
    const float* score_pred = (const float*)d_in[0];
    // d_in[1] = map2d_mask (deterministic triu(ones)) — computed analytically
    const float* map2d      = (const float*)d_in[2];
    const float* offset_gt  = (const float*)d_in[3];
    const float* tmap       = (const float*)d_in[4];
    float* out = (float*)d_out;

    cudaFuncSetAttribute(aps_kernel, cudaFuncAttributeMaxDynamicSharedMemorySize,
                         SMEM_BYTES);
    aps_kernel<<<NB, 1024, SMEM_BYTES>>>(score_pred, map2d, offset_gt, tmap, out);
}

// round 6
// speedup vs baseline: 1.9032x; 1.2380x over previous
#include <cuda_runtime.h>
#include <cuda_bf16.h>
#include <stdint.h>

// Problem constants
#define NB      32
#define NN      64
#define MV      2080          // NN*(NN+1)/2
#define MAIN    2048
#define NEXTRA  32
#define TOPK    5
#define NEIGHBOR 16
#define NEGATIVE 16
#define TOTAL   85            // TOPK*(NEIGHBOR+1)
#define KOUT    101           // NEGATIVE + TOTAL
#define DFEAT   512

// dynamic smem layout (byte offsets)
#define OFF_FKEY    0          // u64[2080]  16640
#define OFF_MKEY    16640      // u64[2048]  16384
#define OFF_EXTRA   33024      // u64[32]      256
#define OFF_MOM     33280      // u32[2080]   8320
#define OFF_RR      41600      // u8[2080]
#define OFF_CC      43680      // u8[2080]
#define OFF_SUP     45760      // u8[2080]
#define OFF_SEL     47840      // u8[2080]
#define OFF_UNSUP   49920      // u16[2080]   4160
#define OFF_SELIDX  54080      // u16[96]
#define OFF_WSUM    54272      // int[34]
#define OFF_FR      54408      // int[101]
#define OFF_FC      54812      // int[101]
#define SMEM_BYTES  55296

__device__ __forceinline__ void cas64(unsigned long long& a, unsigned long long& b, bool dir) {
    // dir true -> descending (a >= b)
    unsigned long long x = a, y = b;
    bool sw = dir ? (x < y) : (x > y);
    a = sw ? y : x;
    b = sw ? x : y;
}

// Register/shuffle stages for bitonic merge step k, levels j = J0 down to 1.
// Thread t owns elements i = 4t + v; a warp holds 128 consecutive elements.
template<int J0>
__device__ __forceinline__ void reg_stages(unsigned long long e[4], int tid, int lane, int k) {
    const int base = tid * 4;
    const bool dirU = ((base & k) == 0);
#pragma unroll
    for (int j = J0; j >= 4; j >>= 1) {
        int lm = j >> 2;
        bool lower = ((lane & lm) == 0);
        bool keepMax = (lower == dirU);
#pragma unroll
        for (int v = 0; v < 4; v++) {
            unsigned long long p = __shfl_xor_sync(0xffffffffu, e[v], lm);
            unsigned long long mx = e[v] > p ? e[v] : p;
            unsigned long long mn = e[v] > p ? p : e[v];
            e[v] = keepMax ? mx : mn;
        }
    }
    if (J0 >= 2) {
        cas64(e[0], e[2], dirU);
        cas64(e[1], e[3], dirU);
    }
    if (k == 2) {
        cas64(e[0], e[1], true);
        cas64(e[2], e[3], false);
    } else {
        cas64(e[0], e[1], dirU);
        cas64(e[2], e[3], dirU);
    }
}

// Two levels (2j, j) of merge k over 2048 elems; 512 threads, one 4-group each.
__device__ __forceinline__ void pass2(unsigned long long* a, int k, int j, int lg, int tid) {
    int low  = tid & (j - 1);
    int hi   = tid >> lg;
    int base = (hi << (lg + 2)) | low;
    unsigned long long e0 = a[base], e1 = a[base + j], e2 = a[base + 2 * j], e3 = a[base + 3 * j];
    bool dir = ((base & k) == 0);
    cas64(e0, e2, dir); cas64(e1, e3, dir);
    cas64(e0, e1, dir); cas64(e2, e3, dir);
    a[base] = e0; a[base + j] = e1; a[base + 2 * j] = e2; a[base + 3 * j] = e3;
}

// Single level j=128 of merge k; 512 threads, two pairs each.
__device__ __forceinline__ void single128(unsigned long long* a, int k, int tid) {
#pragma unroll
    for (int rep = 0; rep < 2; rep++) {
        int p = tid + rep * 512;               // 1024 pairs
        int i = ((p >> 7) << 8) | (p & 127);
        unsigned long long x = a[i], y = a[i + 128];
        bool dir = ((i & k) == 0);
        bool sw = dir ? (x < y) : (x > y);
        if (sw) { a[i] = y; a[i + 128] = x; }
    }
}

template<bool WANT_TRUE>
__device__ __forceinline__ int compact2080(const unsigned char* flags,
                                           unsigned short* out, int* wsum) {
    int tid = threadIdx.x, lane = tid & 31, wid = tid >> 5;
    bool pr[3]; int local = 0;
#pragma unroll
    for (int u = 0; u < 3; u++) {
        int j = 3 * tid + u;
        bool f = (j < MV) && ((flags[j] != 0) == WANT_TRUE);
        pr[u] = f; local += (int)f;
    }
    int x = local;
#pragma unroll
    for (int d = 1; d < 32; d <<= 1) {
        int y = __shfl_up_sync(0xffffffffu, x, d);
        if (lane >= d) x += y;
    }
    if (lane == 31) wsum[wid] = x;
    __syncthreads();
    if (wid == 0) {
        int v = wsum[lane];
        int xx = v;
#pragma unroll
        for (int d = 1; d < 32; d <<= 1) {
            int y = __shfl_up_sync(0xffffffffu, xx, d);
            if (lane >= d) xx += y;
        }
        wsum[lane] = xx - v;
        if (lane == 31) wsum[32] = xx;
    }
    __syncthreads();
    int base = wsum[wid] + x - local;
#pragma unroll
    for (int u = 0; u < 3; u++) {
        if (pr[u]) out[base++] = (unsigned short)(3 * tid + u);
    }
    int total = wsum[32];
    __syncthreads();
    return total;
}

__global__ __launch_bounds__(1024, 1)
void aps_kernel(const float* __restrict__ score_pred,
                const float* __restrict__ map2d,
                const float* __restrict__ offset_gt,
                const float* __restrict__ tmap,
                float* __restrict__ out) {
    extern __shared__ char smem[];
    unsigned long long* fkey  = (unsigned long long*)(smem + OFF_FKEY);
    unsigned long long* mkey  = (unsigned long long*)(smem + OFF_MKEY);
    unsigned long long* extra = (unsigned long long*)(smem + OFF_EXTRA);
    unsigned*       mom  = (unsigned*)      (smem + OFF_MOM);
    unsigned char*  rr   = (unsigned char*) (smem + OFF_RR);
    unsigned char*  cc   = (unsigned char*) (smem + OFF_CC);
    unsigned char*  sup  = (unsigned char*) (smem + OFF_SUP);
    unsigned char*  sel  = (unsigned char*) (smem + OFF_SEL);
    unsigned short* unsupIdx = (unsigned short*)(smem + OFF_UNSUP);
    unsigned short* selIdx   = (unsigned short*)(smem + OFF_SELIDX);
    int* wsum = (int*)(smem + OFF_WSUM);
    int* fr   = (int*)(smem + OFF_FR);
    int* fc   = (int*)(smem + OFF_FC);

    const int b    = blockIdx.x;
    const int tid  = threadIdx.x;
    const int lane = tid & 31, wid = tid >> 5;
    const bool sorter = (wid < 16);   // 512 sorting threads

    // --- 1. (r,c) tables for triu mask in row-major nonzero order ---
    if (tid < NN) {
        int r = tid;
        int base = r * NN - (r * (r - 1)) / 2;
        for (int c = r; c < NN; c++) {
            int p = base + (c - r);
            rr[p] = (unsigned char)r;
            cc[p] = (unsigned char)c;
        }
    }
    __syncthreads();

    // --- 2. build keys. key = (orderable_f32 << 32) | (2079 - p)  (stable ties) ---
    unsigned long long e[4];
    if (sorter) {
#pragma unroll
        for (int v = 0; v < 4; v++) {
            int p = tid * 4 + v;     // p < 2048
            int r = rr[p], c = cc[p];
            float s = score_pred[((size_t)b * NN + r) * NN + c];
            unsigned ub = __float_as_uint(s);
            ub = (ub & 0x80000000u) ? ~ub : (ub | 0x80000000u);
            e[v] = ((unsigned long long)ub << 32) | (unsigned)(2079 - p);
        }
        // --- 3a. register bitonic: sorted 128-runs ---
        reg_stages<1 >(e, tid, lane, 2);
        reg_stages<2 >(e, tid, lane, 4);
        reg_stages<4 >(e, tid, lane, 8);
        reg_stages<8 >(e, tid, lane, 16);
        reg_stages<16>(e, tid, lane, 32);
        reg_stages<32>(e, tid, lane, 64);
        reg_stages<64>(e, tid, lane, 128);
    } else if (wid == 16) {
        // --- 3b. warp 16: sort the 32 extras entirely with shuffles ---
        int p = MAIN + lane;         // 2048..2079
        int r = rr[p], c = cc[p];
        float s = score_pred[((size_t)b * NN + r) * NN + c];
        unsigned ub = __float_as_uint(s);
        ub = (ub & 0x80000000u) ? ~ub : (ub | 0x80000000u);
        unsigned long long x = ((unsigned long long)ub << 32) | (unsigned)(2079 - p);
#pragma unroll
        for (int k2 = 2; k2 <= 32; k2 <<= 1) {
            bool dirk = ((lane & k2) == 0);
#pragma unroll
            for (int j2 = 16; j2 >= 1; j2 >>= 1) {
                if (j2 < k2) {
                    unsigned long long pr = __shfl_xor_sync(0xffffffffu, x, j2);
                    bool keepMax = (((lane & j2) == 0) == dirk);
                    unsigned long long mx = x > pr ? x : pr;
                    unsigned long long mn = x > pr ? pr : x;
                    x = keepMax ? mx : mn;
                }
            }
        }
        extra[lane] = x;             // descending
    }

    // --- 3c. merges k=256..2048: hybrid smem(two-level) + register stages ---
#pragma unroll 1
    for (int k = 256; k <= MAIN; k <<= 1) {
        if (sorter) {
#pragma unroll
            for (int v = 0; v < 4; v++) mkey[tid * 4 + v] = e[v];
        }
        __syncthreads();
        if (k == 256) {
            if (sorter) single128(mkey, k, tid);
        } else if (k == 512) {
            if (sorter) pass2(mkey, k, 128, 7, tid);
        } else if (k == 1024) {
            if (sorter) pass2(mkey, k, 256, 8, tid);
            __syncthreads();
            if (sorter) single128(mkey, k, tid);
        } else { // k == 2048
            if (sorter) pass2(mkey, k, 512, 9, tid);
            __syncthreads();
            if (sorter) pass2(mkey, k, 128, 7, tid);
        }
        __syncthreads();
        if (sorter) {
#pragma unroll
            for (int v = 0; v < 4; v++) e[v] = mkey[tid * 4 + v];
            reg_stages<64>(e, tid, lane, k);
        }
    }

    // --- 3d. publish sorted main run, then rank-merge with extras ---
    if (sorter) {
#pragma unroll
        for (int v = 0; v < 4; v++) mkey[tid * 4 + v] = e[v];
    }
    __syncthreads();
    if (sorter) {
#pragma unroll
        for (int v = 0; v < 4; v++) {
            unsigned long long x = e[v];
            int lo = 0, hiS = NEXTRA;          // count extras > x (desc array)
            while (lo < hiS) {
                int mid = (lo + hiS) >> 1;
                if (extra[mid] > x) lo = mid + 1; else hiS = mid;
            }
            fkey[tid * 4 + v + lo] = x;
        }
    } else if (wid == 16) {
        unsigned long long x = extra[lane];
        int lo = 0, hiS = MAIN;                // count mains > x
        while (lo < hiS) {
            int mid = (lo + hiS) >> 1;
            if (mkey[mid] > x) lo = mid + 1; else hiS = mid;
        }
        fkey[lo + lane] = x;
    }
    __syncthreads();

    // --- 4. sorted packed moments + clear bitmaps ---
    for (int i = tid; i < MV; i += 1024) {
        int orig = 2079 - (int)(unsigned)(fkey[i] & 0xFFFFFFFFull);
        unsigned s = rr[orig];
        unsigned en = (unsigned)cc[orig] + 1u;
        mom[i] = s | (en << 16);
        sup[i] = 0; sel[i] = 0;
    }
    __syncthreads();

    // --- 5. NMS selection loop (warp 0 only) ---
    if (wid == 0) {
        int i = 0, cnt = 0;
        while (cnt < TOPK) {
            int piv = -1;
            for (int base = i; base < MV - 1; base += 32) {
                int j = base + lane;
                bool ok = (j < MV - 1) && (sup[j] == 0);
                unsigned bl = __ballot_sync(0xffffffffu, ok);
                if (bl) { piv = base + __ffs(bl) - 1; break; }
            }
            if (piv < 0) break;
            unsigned mp = mom[piv];
            int s_i = (int)(mp & 0xffffu), e_i = (int)(mp >> 16);

            unsigned long long mlo = 0ull; unsigned mhi = 0u;
            int localCount = 0;
#pragma unroll 13
            for (int u = 0; u < 65; u++) {
                int j = lane * 65 + u;
                bool match = false;
                if (j < MV && j > piv) {
                    unsigned m = mom[j];
                    int sj = (int)(m & 0xffffu), ej = (int)(m >> 16);
                    int inter = min(ej, e_i) - max(sj, s_i);
                    int uni   = max(ej, e_i) - min(sj, s_i);
                    match = (2 * inter > uni);
                }
                if (match) {
                    localCount++;
                    if (u < 64) mlo |= (1ull << u); else mhi |= 1u;
                }
            }
            int x = localCount;
#pragma unroll
            for (int d = 1; d < 32; d <<= 1) {
                int y = __shfl_up_sync(0xffffffffu, x, d);
                if (lane >= d) x += y;
            }
            int run = x - localCount;
#pragma unroll 13
            for (int u = 0; u < 65; u++) {
                bool match = (u < 64) ? (((mlo >> u) & 1ull) != 0ull) : (mhi != 0u);
                if (match) {
                    int j = lane * 65 + u;
                    sup[j] = 1;
                    run++;
                    if (run <= NEIGHBOR) sel[j] = 1;
                }
            }
            if (lane == 0) { sup[piv] = 1; sel[piv] = 1; }
            __syncwarp();
            cnt++;
            i = piv + 1;
        }
    }
    __syncthreads();

    // --- 6. stable compactions ---
    int nUnsup = compact2080<false>(sup, unsupIdx, wsum);
    int nSel   = compact2080<true >(sel, selIdx,   wsum);

    // --- 7. final index assembly + small outputs ---
    float* feat = out;
    float* se   = out + (size_t)NB * KOUT * DFEAT;
    float* off  = se  + (size_t)NB * KOUT * 2;
    float* sc   = off + (size_t)NB * KOUT * 2;

    if (tid < KOUT) {
        int k = tid;
        int val;
        if (k < NEGATIVE) {
            int pos = nUnsup - 1 - k;
            if (pos < 0) pos = 0;
            val = (pos < nUnsup) ? (int)unsupIdx[pos] : (MV - 1);
        } else {
            int p = k - NEGATIVE;
            int pad = TOTAL - nSel;
            if (p < pad) {
                val = (p < nUnsup) ? (int)unsupIdx[p] : (MV - 1);
            } else {
                val = (int)selIdx[p - pad];
            }
        }
        int orig = 2079 - (int)(unsigned)(fkey[val] & 0xFFFFFFFFull);
        int r = rr[orig], c = cc[orig];
        fr[k] = r; fc[k] = c;

        size_t o = (size_t)b * KOUT + k;
        se[o * 2 + 0] = (float)r;
        se[o * 2 + 1] = (float)(c + 1);
        size_t cell = ((size_t)b * NN + r) * NN + c;
        off[o * 2 + 0] = offset_gt[cell * 2 + 0];
        off[o * 2 + 1] = offset_gt[cell * 2 + 1];
        sc[o] = tmap[cell];
    }
    __syncthreads();

    // --- 8. feature gather (float4, coalesced 2KB rows) ---
    const float4* src = (const float4*)map2d;
    float4* dst = (float4*)feat;
    const int VEC = DFEAT / 4;   // 128
    for (int t = tid; t < KOUT * VEC; t += 1024) {
        int k = t >> 7;
        int d = t & (VEC - 1);
        int r = fr[k], c = fc[k];
        dst[((size_t)b * KOUT + k) * VEC + d] =
            src[(((size_t)b * NN + r) * NN + c) * VEC + d];
    }
}

extern "C" void kernel_launch(void* const* d_in, const int* in_sizes, int n_in,
                              void* d_out, int out_size) {
    const float* score_pred = (const float*)d_in[0];
    // d_in[1] = map2d_mask (deterministic triu(ones)) — computed analytically
    const float* map2d      = (const float*)d_in[2];
    const float* offset_gt  = (const float*)d_in[3];
    const float* tmap       = (const float*)d_in[4];
    float* out = (float*)d_out;

    cudaFuncSetAttribute(aps_kernel, cudaFuncAttributeMaxDynamicSharedMemorySize,
                         SMEM_BYTES);
    aps_kernel<<<NB, 1024, SMEM_BYTES>>>(score_pred, map2d, offset_gt, tmap, out);
}